// round 7
// baseline (speedup 1.0000x reference)
#include <cuda_runtime.h>
#include <cstdint>

#define Bsz 32
#define Ssz 512
#define INsz 300
#define Hsz 180
#define GHsz 720
#define OUTsz 60

// ---------------- scratch (static device globals; no allocation) ----------------
__device__ float g_G[Bsz * Ssz * GHsz];    // gate preactivations [M,720]  (47 MB)
__device__ float g_HS[Bsz * Ssz * Hsz];    // layer hidden states [M,180]
__device__ float g_lin[Bsz * Ssz * OUTsz]; // lstm60 ("lstm_out") [B,S,60]
__device__ float g_mA[Bsz * Ssz * OUTsz];
__device__ float g_mB[Bsz * Ssz * OUTsz];

// ---------------- GEMM: C[m,n] = sum_k A[m,k]*W[n,k] + b1[n] + b2[n] ----------------
#define BM 64
#define BN 64
#define BK 20
#define LDS_ 68

__global__ __launch_bounds__(256) void gemm_nt(
    const float* __restrict__ A, int lda,
    const float* __restrict__ W,   // [N,K] row-major
    const float* __restrict__ b1,
    const float* __restrict__ b2,
    float* __restrict__ C, int ldc,
    int M, int N, int K)
{
    __shared__ float As[BK * LDS_];
    __shared__ float Bs[BK * LDS_];
    int tid = threadIdx.x;
    int tx = tid & 15, ty = tid >> 4;
    int m0 = blockIdx.y * BM, n0 = blockIdx.x * BN;
    float acc[4][4];
#pragma unroll
    for (int i = 0; i < 4; i++)
#pragma unroll
        for (int j = 0; j < 4; j++) acc[i][j] = 0.f;

    for (int k0 = 0; k0 < K; k0 += BK) {
#pragma unroll
        for (int i = 0; i < 5; i++) {
            int e = i * 256 + tid;          // 0..1279
            int ml = e / BK;
            int kl = e - ml * BK;
            int m = m0 + ml;
            As[kl * LDS_ + ml] = (m < M) ? A[(size_t)m * lda + k0 + kl] : 0.f;
            int n = n0 + ml;
            Bs[kl * LDS_ + ml] = (n < N) ? W[(size_t)n * K + k0 + kl] : 0.f;
        }
        __syncthreads();
#pragma unroll
        for (int kk = 0; kk < BK; kk++) {
            float4 a4 = *reinterpret_cast<const float4*>(&As[kk * LDS_ + ty * 4]);
            float4 b4 = *reinterpret_cast<const float4*>(&Bs[kk * LDS_ + tx * 4]);
            float a[4] = {a4.x, a4.y, a4.z, a4.w};
            float b[4] = {b4.x, b4.y, b4.z, b4.w};
#pragma unroll
            for (int i = 0; i < 4; i++)
#pragma unroll
                for (int j = 0; j < 4; j++) acc[i][j] += a[i] * b[j];
        }
        __syncthreads();
    }
#pragma unroll
    for (int i = 0; i < 4; i++) {
        int m = m0 + ty * 4 + i;
        if (m >= M) continue;
#pragma unroll
        for (int j = 0; j < 4; j++) {
            int n = n0 + tx * 4 + j;
            if (n >= N) continue;
            float bias = 0.f;
            if (b1) bias += b1[n];
            if (b2) bias += b2[n];
            C[(size_t)m * ldc + n] = acc[i][j] + bias;
        }
    }
}

// ---------------- LSTM recurrence (cluster of 4 CTAs per batch element) ----------------
__device__ __forceinline__ float sigm(float x) { return 1.f / (1.f + __expf(-x)); }

__device__ __forceinline__ uint32_t smem_u32(const void* p) {
    return (uint32_t)__cvta_generic_to_shared(p);
}

__device__ __forceinline__ void st_cluster_f32(uint32_t addr, uint32_t rank, float v) {
    uint32_t ra;
    asm volatile("mapa.shared::cluster.u32 %0, %1, %2;" : "=r"(ra) : "r"(addr), "r"(rank));
    asm volatile("st.shared::cluster.f32 [%0], %1;" :: "r"(ra), "f"(v) : "memory");
}

__global__ __launch_bounds__(384, 1) __cluster_dims__(4, 1, 1)
void lstm_recur(const float* __restrict__ Whh_l,   // [720,180] this layer
                const float* __restrict__ G,       // [B*S,720] preact incl. biases
                float* __restrict__ HS)            // [B*S,180] out
{
    __shared__ float h_sh[2][192];   // double-buffered hidden state
    __shared__ float pre_sh[184];    // gate preactivations for this CTA's 180 rows

    int t = threadIdx.x;
    int batch = blockIdx.x >> 2;
    int rank  = blockIdx.x & 3;
    int u0 = rank * 45;              // this CTA owns hidden units [u0, u0+45)
    int r = t >> 1;                  // local gate-row 0..179 (2 threads per row)
    int half = t & 1;
    bool active = (t < 360);
    int gate = r / 45;
    int uu = r - gate * 45;
    int row_global = gate * 180 + u0 + uu;   // (i,f,g,o) blocks of 180

    float w[90];
    if (active) {
        const float* wr = Whh_l + (size_t)row_global * Hsz + half * 90;
#pragma unroll
        for (int k = 0; k < 90; k++) w[k] = wr[k];
    }
    if (t < 192) { h_sh[0][t] = 0.f; h_sh[1][t] = 0.f; }
    float c = 0.f;

    asm volatile("barrier.cluster.arrive.aligned;" ::: "memory");
    asm volatile("barrier.cluster.wait.aligned;" ::: "memory");

    const float* Gb = G + (size_t)batch * Ssz * GHsz;
    float* HSb = HS + (size_t)batch * Ssz * Hsz;

    for (int s = 0; s < Ssz; s++) {
        int cur = s & 1;
        float acc = 0.f;
        if (active) {
            const float2* hb = reinterpret_cast<const float2*>(&h_sh[cur][half * 90]);
#pragma unroll
            for (int k = 0; k < 45; k++) {
                float2 hv = hb[k];
                acc = fmaf(w[2 * k],     hv.x, acc);
                acc = fmaf(w[2 * k + 1], hv.y, acc);
            }
        }
        float other = __shfl_xor_sync(0xffffffffu, acc, 1);
        if (active && half == 0)
            pre_sh[r] = acc + other + Gb[(size_t)s * GHsz + row_global];
        __syncthreads();

        if (t < 45) {
            float gi = pre_sh[t];
            float gf = pre_sh[45 + t];
            float gg = pre_sh[90 + t];
            float go = pre_sh[135 + t];
            c = sigm(gf) * c + sigm(gi) * tanhf(gg);
            float hn = sigm(go) * tanhf(c);
            uint32_t la = smem_u32(&h_sh[cur ^ 1][u0 + t]);
#pragma unroll
            for (uint32_t p = 0; p < 4; p++) st_cluster_f32(la, p, hn);
            HSb[(size_t)s * Hsz + u0 + t] = hn;
        }
        // one cluster barrier per step: publishes buf[cur^1], and guarantees
        // everyone finished reading buf[cur] of this step before it's rewritten
        // two steps later.
        asm volatile("barrier.cluster.arrive.aligned;" ::: "memory");
        asm volatile("barrier.cluster.wait.aligned;" ::: "memory");
    }
}

// ---------------- mel smoothing block: 3x5 stencil + residual ----------------
__global__ void mel_kernel(const float* __restrict__ X, const float* __restrict__ w,
                           const float* __restrict__ bias, float* __restrict__ Y, int l)
{
    int idx = blockIdx.x * blockDim.x + threadIdx.x;
    const int TOT = Bsz * Ssz * OUTsz;
    if (idx >= TOT) return;
    int c = idx % OUTsz;
    int sb = idx / OUTsz;
    int s = sb % Ssz;
    int b = sb / Ssz;
    int j = c % 3, i = c / 3;
    const float* wp = w + ((size_t)(l * 3 + j) * 20 + i) * 15;   // mel_w[l][j][i][.][.]
    float acc = X[idx] + bias[(l * 3 + j) * 20 + i];
    const float* Xb = X + (size_t)b * Ssz * OUTsz;
#pragma unroll
    for (int d = 0; d < 3; d++) {
        int cc = c + d - 1;
        if (cc < 0 || cc >= OUTsz) continue;
#pragma unroll
        for (int k = 0; k < 5; k++) {
            int ss = s + k - 2;
            if (ss < 0 || ss >= Ssz) continue;
            acc += Xb[ss * OUTsz + cc] * wp[d * 5 + k];
        }
    }
    Y[idx] = acc;
}

// ---------------- residual conv: (lstm, smoothed) interleave, groups=60 ----------------
__global__ void res_kernel(const float* __restrict__ Lm, const float* __restrict__ Sm,
                           const float* __restrict__ resW, const float* __restrict__ resb,
                           float* __restrict__ Y)
{
    int idx = blockIdx.x * blockDim.x + threadIdx.x;
    const int TOT = Bsz * Ssz * OUTsz;
    if (idx >= TOT) return;
    int c = idx % OUTsz;
    int sb = idx / OUTsz;
    int s = sb % Ssz;
    int b = sb / Ssz;
    const float* Lb = Lm + (size_t)b * Ssz * OUTsz;
    const float* Sb = Sm + (size_t)b * Ssz * OUTsz;
    float acc = resb[c];
#pragma unroll
    for (int k = 0; k < 5; k++) {
        int ss = s + k - 2;
        if (ss < 0 || ss >= Ssz) continue;
        acc += Lb[ss * OUTsz + c] * resW[c * 10 + k];        // resW[c][0][k]
        acc += Sb[ss * OUTsz + c] * resW[c * 10 + 5 + k];    // resW[c][1][k]
    }
    Y[idx] = acc;   // output layout [B,S,60]
}

// ---------------- launcher ----------------
extern "C" void kernel_launch(void* const* d_in, const int* in_sizes, int n_in,
                              void* d_out, int out_size)
{
    const float* x        = (const float*)d_in[0];
    const float* Wih0     = (const float*)d_in[1];
    const float* Wih_rest = (const float*)d_in[2];
    const float* Whh      = (const float*)d_in[3];
    const float* bih      = (const float*)d_in[4];
    const float* bhh      = (const float*)d_in[5];
    const float* linW     = (const float*)d_in[6];
    const float* linb     = (const float*)d_in[7];
    const float* mel_w    = (const float*)d_in[8];
    const float* mel_b    = (const float*)d_in[9];
    const float* resW     = (const float*)d_in[10];
    const float* resb     = (const float*)d_in[11];
    float* out = (float*)d_out;

    float *pG, *pHS, *pLin, *pA, *pB;
    cudaGetSymbolAddress((void**)&pG,   g_G);
    cudaGetSymbolAddress((void**)&pHS,  g_HS);
    cudaGetSymbolAddress((void**)&pLin, g_lin);
    cudaGetSymbolAddress((void**)&pA,   g_mA);
    cudaGetSymbolAddress((void**)&pB,   g_mB);

    const int M = Bsz * Ssz;          // 16384
    dim3 blk(256);
    dim3 gg((GHsz + BN - 1) / BN, (M + BM - 1) / BM);   // 12 x 256

    // layer 0
    gemm_nt<<<gg, blk>>>(x, INsz, Wih0, bih, bhh, pG, GHsz, M, GHsz, INsz);
    lstm_recur<<<128, 384>>>(Whh, pG, pHS);
    // layers 1..3
    for (int l = 1; l < 4; l++) {
        gemm_nt<<<gg, blk>>>(pHS, Hsz, Wih_rest + (size_t)(l - 1) * GHsz * Hsz,
                             bih + l * GHsz, bhh + l * GHsz, pG, GHsz, M, GHsz, Hsz);
        lstm_recur<<<128, 384>>>(Whh + (size_t)l * GHsz * Hsz, pG, pHS);
    }
    // linear to 60 channels  (output layout [B,S,60])
    dim3 gl(1, (M + BM - 1) / BM);
    gemm_nt<<<gl, blk>>>(pHS, Hsz, linW, linb, nullptr, pLin, OUTsz, M, OUTsz, Hsz);

    const int tot = Bsz * Ssz * OUTsz;
    int nb = (tot + 255) / 256;
    mel_kernel<<<nb, 256>>>(pLin, mel_w, mel_b, pA, 0);
    mel_kernel<<<nb, 256>>>(pA,   mel_w, mel_b, pB, 1);
    mel_kernel<<<nb, 256>>>(pB,   mel_w, mel_b, pA, 2);
    res_kernel<<<nb, 256>>>(pLin, pA, resW, resb, out);
}

// round 8
// speedup vs baseline: 1.5131x; 1.5131x over previous
#include <cuda_runtime.h>
#include <cstdint>

#define Bsz 32
#define Ssz 512
#define INsz 300
#define Hsz 180
#define GHsz 720
#define OUTsz 60
#define Msz (Bsz * Ssz)   // 16384

// ---------------- scratch (static device globals; no allocation) ----------------
__device__ float g_xT[INsz * Msz];      // x^T       [300][M]
__device__ float g_WT[INsz * GHsz];     // W^T scratch (max 300x720)
__device__ float g_G [GHsz * Msz];      // gate preact [720][M]
__device__ float g_HT[Hsz * Msz];       // h^T        [180][M]
__device__ float g_linT[OUTsz * Msz];   // lstm60^T   [60][M]
__device__ float g_mA[OUTsz * Msz];
__device__ float g_mB[OUTsz * Msz];

// ---------------- generic tiled transpose: in[R][C] -> out[C][R] ----------------
__global__ void transpose_k(const float* __restrict__ in, float* __restrict__ out,
                            int R, int C)
{
    __shared__ float t[32][33];
    int r0 = blockIdx.y * 32, c0 = blockIdx.x * 32;
#pragma unroll
    for (int i = 0; i < 32; i += 8) {
        int r = r0 + threadIdx.y + i, c = c0 + threadIdx.x;
        if (r < R && c < C) t[threadIdx.y + i][threadIdx.x] = in[(size_t)r * C + c];
    }
    __syncthreads();
#pragma unroll
    for (int i = 0; i < 32; i += 8) {
        int rr = c0 + threadIdx.y + i, cc = r0 + threadIdx.x;
        if (rr < C && cc < R) out[(size_t)rr * R + cc] = t[threadIdx.x][threadIdx.y + i];
    }
}

// ---------------- GEMM (both operands k-major):
//   C[n][m] = sum_k AT[k][m] * WT[k][n] + b1[n] + b2[n]
// 128x128x16 tiles, 256 threads, 8x8 microtile, register-prefetch pipeline.
#define GBM 128
#define GBN 128
#define GBK 16

__global__ __launch_bounds__(256) void gemm_tt(
    const float* __restrict__ AT,   // [K][M]
    const float* __restrict__ WT,   // [K][N]
    const float* __restrict__ b1,
    const float* __restrict__ b2,
    float* __restrict__ C,          // [N][M]
    int M, int N, int K)
{
    __shared__ float As[GBK][GBM];
    __shared__ float Bs[GBK][GBN];
    int tid = threadIdx.x;
    int m0 = blockIdx.x * GBM, n0 = blockIdx.y * GBN;

    int lk = tid >> 5;          // loader row 0..7 (+8)
    int lq = tid & 31;          // loader float4 col
    int tm = tid & 15;          // compute: m microtile index
    int tn = tid >> 4;          // compute: n microtile index

    float acc[8][8];
#pragma unroll
    for (int i = 0; i < 8; i++)
#pragma unroll
        for (int j = 0; j < 8; j++) acc[i][j] = 0.f;

    const float4 z4 = make_float4(0.f, 0.f, 0.f, 0.f);
    float4 pa[2], pb[2];
    bool nvalid = (n0 + lq * 4 + 3) < N;

    // prefetch chunk 0
#pragma unroll
    for (int i = 0; i < 2; i++) {
        int k = lk + i * 8;
        pa[i] = (k < K) ? *reinterpret_cast<const float4*>(&AT[(size_t)k * M + m0 + lq * 4]) : z4;
        pb[i] = (k < K && nvalid) ? *reinterpret_cast<const float4*>(&WT[(size_t)k * N + n0 + lq * 4]) : z4;
    }

    int nch = (K + GBK - 1) / GBK;
    for (int ch = 0; ch < nch; ch++) {
        __syncthreads();   // previous compute done reading smem
#pragma unroll
        for (int i = 0; i < 2; i++) {
            *reinterpret_cast<float4*>(&As[lk + i * 8][lq * 4]) = pa[i];
            *reinterpret_cast<float4*>(&Bs[lk + i * 8][lq * 4]) = pb[i];
        }
        __syncthreads();
        if (ch + 1 < nch) {
            int k0 = (ch + 1) * GBK;
#pragma unroll
            for (int i = 0; i < 2; i++) {
                int k = k0 + lk + i * 8;
                pa[i] = (k < K) ? *reinterpret_cast<const float4*>(&AT[(size_t)k * M + m0 + lq * 4]) : z4;
                pb[i] = (k < K && nvalid) ? *reinterpret_cast<const float4*>(&WT[(size_t)k * N + n0 + lq * 4]) : z4;
            }
        }
#pragma unroll
        for (int kk = 0; kk < GBK; kk++) {
            float4 a0 = *reinterpret_cast<const float4*>(&As[kk][tm * 8]);
            float4 a1 = *reinterpret_cast<const float4*>(&As[kk][tm * 8 + 4]);
            float4 b0 = *reinterpret_cast<const float4*>(&Bs[kk][tn * 8]);
            float4 b1v = *reinterpret_cast<const float4*>(&Bs[kk][tn * 8 + 4]);
            float a[8] = {a0.x, a0.y, a0.z, a0.w, a1.x, a1.y, a1.z, a1.w};
            float b[8] = {b0.x, b0.y, b0.z, b0.w, b1v.x, b1v.y, b1v.z, b1v.w};
#pragma unroll
            for (int j = 0; j < 8; j++)
#pragma unroll
                for (int i = 0; i < 8; i++)
                    acc[j][i] = fmaf(a[i], b[j], acc[j][i]);
        }
    }

#pragma unroll
    for (int j = 0; j < 8; j++) {
        int n = n0 + tn * 8 + j;
        if (n >= N) continue;
        float bias = (b1 ? b1[n] : 0.f) + (b2 ? b2[n] : 0.f);
        float* crow = &C[(size_t)n * M + m0 + tm * 8];
        float4 v0 = make_float4(acc[j][0] + bias, acc[j][1] + bias, acc[j][2] + bias, acc[j][3] + bias);
        float4 v1 = make_float4(acc[j][4] + bias, acc[j][5] + bias, acc[j][6] + bias, acc[j][7] + bias);
        *reinterpret_cast<float4*>(crow)     = v0;
        *reinterpret_cast<float4*>(crow + 4) = v1;
    }
}

// ---------------- LSTM recurrence (cluster of 4 CTAs per batch element) ----------------
__device__ __forceinline__ float tanha(float x) {
    float y; asm("tanh.approx.f32 %0, %1;" : "=f"(y) : "f"(x)); return y;
}
__device__ __forceinline__ float sigm(float x) { return 0.5f * tanha(0.5f * x) + 0.5f; }

__device__ __forceinline__ uint32_t smem_u32(const void* p) {
    return (uint32_t)__cvta_generic_to_shared(p);
}
__device__ __forceinline__ void st_cluster_f32(uint32_t addr, uint32_t rank, float v) {
    uint32_t ra;
    asm volatile("mapa.shared::cluster.u32 %0, %1, %2;" : "=r"(ra) : "r"(addr), "r"(rank));
    asm volatile("st.shared::cluster.f32 [%0], %1;" :: "r"(ra), "f"(v) : "memory");
}

__global__ __launch_bounds__(192, 1) __cluster_dims__(4, 1, 1)
void lstm_recur(const float* __restrict__ Whh_l,   // [720][180] this layer (row-major)
                const float* __restrict__ G,       // [720][M] preact incl. biases
                float* __restrict__ HT)            // [180][M] out (transposed)
{
    __shared__ float h_sh[2][184];   // double-buffered hidden state (full 180)
    __shared__ float pre_sh[184];    // this CTA's 180 gate preactivations

    int t = threadIdx.x;
    int batch = blockIdx.x >> 2;
    int rank  = blockIdx.x & 3;
    int u0 = rank * 45;              // this CTA owns hidden units [u0, u0+45)
    bool act = (t < 180);
    int gate = t / 45;
    int uu = t - gate * 45;
    int row_global = gate * 180 + u0 + uu;   // (i,f,g,o) blocks of 180

    // entire Whh row in registers (180 floats)
    float w[180];
    if (act) {
        const float* wr = Whh_l + (size_t)row_global * Hsz;
#pragma unroll
        for (int k = 0; k < 180; k++) w[k] = wr[k];
    }
    if (t < 184) { h_sh[0][t] = 0.f; h_sh[1][t] = 0.f; }
    float c = 0.f;

    const float* Grow = G + (act ? ((size_t)row_global * Msz + batch * Ssz) : 0);
    float gnext = act ? Grow[0] : 0.f;
    float* Hrow = HT + (size_t)(u0 + (t < 45 ? t : 0)) * Msz + batch * Ssz;

    asm volatile("barrier.cluster.arrive.aligned;" ::: "memory");
    asm volatile("barrier.cluster.wait.aligned;" ::: "memory");

    for (int s = 0; s < Ssz; s++) {
        int cur = s & 1;
        float gv = gnext;
        if (act && s + 1 < Ssz) gnext = Grow[s + 1];   // prefetch across barrier+FMA

        if (act) {
            const float4* hb = reinterpret_cast<const float4*>(h_sh[cur]);
            float a0 = 0.f, a1 = 0.f, a2 = 0.f, a3 = 0.f;
#pragma unroll
            for (int k = 0; k < 45; k++) {
                float4 h4 = hb[k];
                a0 = fmaf(w[4 * k],     h4.x, a0);
                a1 = fmaf(w[4 * k + 1], h4.y, a1);
                a2 = fmaf(w[4 * k + 2], h4.z, a2);
                a3 = fmaf(w[4 * k + 3], h4.w, a3);
            }
            pre_sh[t] = (a0 + a1) + (a2 + a3) + gv;
        }
        __syncthreads();

        if (t < 45) {
            float gi = pre_sh[t];
            float gf = pre_sh[45 + t];
            float gg = pre_sh[90 + t];
            float go = pre_sh[135 + t];
            c = sigm(gf) * c + sigm(gi) * tanha(gg);
            float hn = sigm(go) * tanha(c);
            uint32_t la = smem_u32(&h_sh[cur ^ 1][u0 + t]);
#pragma unroll
            for (uint32_t p = 0; p < 4; p++) st_cluster_f32(la, p, hn);
            Hrow[s] = hn;
        }
        // one cluster barrier per step: publishes buf[cur^1] everywhere and
        // guarantees this step's reads of buf[cur] finished before it is
        // rewritten two steps later (double-buffer safety).
        asm volatile("barrier.cluster.arrive.aligned;" ::: "memory");
        asm volatile("barrier.cluster.wait.aligned;" ::: "memory");
    }
}

// ---------------- mel smoothing block on [60][M] layout ----------------
__global__ void mel_T(const float* __restrict__ X, const float* __restrict__ w,
                      const float* __restrict__ bias, float* __restrict__ Y, int l)
{
    int m = blockIdx.x * 256 + threadIdx.x;   // 0..M-1
    int cch = blockIdx.y;                     // 0..59
    int s = m & (Ssz - 1);
    int j = cch % 3, i = cch / 3;
    const float* wp = w + ((size_t)(l * 3 + j) * 20 + i) * 15;
    float acc = X[(size_t)cch * Msz + m] + bias[(l * 3 + j) * 20 + i];
#pragma unroll
    for (int d = 0; d < 3; d++) {
        int cc = cch + d - 1;
        if (cc < 0 || cc >= OUTsz) continue;
        const float* row = X + (size_t)cc * Msz + m;
#pragma unroll
        for (int k = 0; k < 5; k++) {
            int ss = s + k - 2;
            if (ss < 0 || ss >= Ssz) continue;
            acc += row[k - 2] * wp[d * 5 + k];
        }
    }
    Y[(size_t)cch * Msz + m] = acc;
}

// ---------------- residual conv on [60][M]; writes m-major output ----------------
__global__ void res_T(const float* __restrict__ Lm, const float* __restrict__ Sm,
                      const float* __restrict__ resW, const float* __restrict__ resb,
                      float* __restrict__ Y)
{
    int m = blockIdx.x * 256 + threadIdx.x;
    int cch = blockIdx.y;
    int s = m & (Ssz - 1);
    const float* Lr = Lm + (size_t)cch * Msz + m;
    const float* Sr = Sm + (size_t)cch * Msz + m;
    float acc = resb[cch];
#pragma unroll
    for (int k = 0; k < 5; k++) {
        int ss = s + k - 2;
        if (ss < 0 || ss >= Ssz) continue;
        acc += Lr[k - 2] * resW[cch * 10 + k];
        acc += Sr[k - 2] * resW[cch * 10 + 5 + k];
    }
    Y[(size_t)m * OUTsz + cch] = acc;   // [B,S,60]
}

// ---------------- launcher ----------------
extern "C" void kernel_launch(void* const* d_in, const int* in_sizes, int n_in,
                              void* d_out, int out_size)
{
    const float* x        = (const float*)d_in[0];
    const float* Wih0     = (const float*)d_in[1];
    const float* Wih_rest = (const float*)d_in[2];
    const float* Whh      = (const float*)d_in[3];
    const float* bih      = (const float*)d_in[4];
    const float* bhh      = (const float*)d_in[5];
    const float* linW     = (const float*)d_in[6];
    const float* linb     = (const float*)d_in[7];
    const float* mel_w    = (const float*)d_in[8];
    const float* mel_b    = (const float*)d_in[9];
    const float* resW     = (const float*)d_in[10];
    const float* resb     = (const float*)d_in[11];
    float* out = (float*)d_out;

    float *pXT, *pWT, *pG, *pHT, *pLin, *pA, *pB;
    cudaGetSymbolAddress((void**)&pXT,  g_xT);
    cudaGetSymbolAddress((void**)&pWT,  g_WT);
    cudaGetSymbolAddress((void**)&pG,   g_G);
    cudaGetSymbolAddress((void**)&pHT,  g_HT);
    cudaGetSymbolAddress((void**)&pLin, g_linT);
    cudaGetSymbolAddress((void**)&pA,   g_mA);
    cudaGetSymbolAddress((void**)&pB,   g_mB);

    dim3 tb(32, 8);
    auto tgrid = [](int R, int C) { return dim3((C + 31) / 32, (R + 31) / 32); };

    // x^T : [M,300] -> [300,M]
    transpose_k<<<tgrid(Msz, INsz), tb>>>(x, pXT, Msz, INsz);

    dim3 gblk(256);
    dim3 gg(Msz / GBM, (GHsz + GBN - 1) / GBN);   // 128 x 6

    // layer 0
    transpose_k<<<tgrid(GHsz, INsz), tb>>>(Wih0, pWT, GHsz, INsz);
    gemm_tt<<<gg, gblk>>>(pXT, pWT, bih, bhh, pG, Msz, GHsz, INsz);
    lstm_recur<<<128, 192>>>(Whh, pG, pHT);

    // layers 1..3
    for (int l = 1; l < 4; l++) {
        transpose_k<<<tgrid(GHsz, Hsz), tb>>>(Wih_rest + (size_t)(l - 1) * GHsz * Hsz,
                                              pWT, GHsz, Hsz);
        gemm_tt<<<gg, gblk>>>(pHT, pWT, bih + l * GHsz, bhh + l * GHsz,
                              pG, Msz, GHsz, Hsz);
        lstm_recur<<<128, 192>>>(Whh + (size_t)l * GHsz * Hsz, pG, pHT);
    }

    // linear to 60 channels, output [60][M]
    transpose_k<<<tgrid(OUTsz, Hsz), tb>>>(linW, pWT, OUTsz, Hsz);
    dim3 gl(Msz / GBM, 1);
    gemm_tt<<<gl, gblk>>>(pHT, pWT, linb, nullptr, pLin, Msz, OUTsz, Hsz);

    // mel smoothing blocks + residual conv
    dim3 cgrid(Msz / 256, OUTsz);
    mel_T<<<cgrid, 256>>>(pLin, mel_w, mel_b, pA, 0);
    mel_T<<<cgrid, 256>>>(pA,   mel_w, mel_b, pB, 1);
    mel_T<<<cgrid, 256>>>(pB,   mel_w, mel_b, pA, 2);
    res_T<<<cgrid, 256>>>(pLin, pA, resW, resb, out);
}

// round 9
// speedup vs baseline: 2.2043x; 1.4568x over previous
#include <cuda_runtime.h>
#include <cstdint>

#define Bsz 32
#define Ssz 512
#define INsz 300
#define Hsz 180
#define GHsz 720
#define OUTsz 60
#define Msz (Bsz * Ssz)   // 16384

// ---------------- scratch (static device globals; no allocation) ----------------
__device__ float g_xT[INsz * Msz];      // x^T       [300][M]
__device__ float g_WT[INsz * GHsz];     // W^T scratch (max 300x720)
__device__ float g_G [GHsz * Msz];      // gate preact [720][M]
__device__ float g_HT[Hsz * Msz];       // h^T        [180][M]
__device__ float g_linT[OUTsz * Msz];   // lstm60^T   [60][M]
__device__ float g_mA[OUTsz * Msz];
__device__ float g_mB[OUTsz * Msz];

// ---------------- f32x2 helpers ----------------
__device__ __forceinline__ unsigned long long fma2(unsigned long long a,
                                                   unsigned long long b,
                                                   unsigned long long c) {
    unsigned long long d;
    asm("fma.rn.f32x2 %0, %1, %2, %3;" : "=l"(d) : "l"(a), "l"(b), "l"(c));
    return d;
}
__device__ __forceinline__ float2 unpk2(unsigned long long v) {
    float2 r;
    asm("mov.b64 {%0, %1}, %2;" : "=f"(r.x), "=f"(r.y) : "l"(v));
    return r;
}
__device__ __forceinline__ unsigned long long splat2(float x) {
    unsigned long long d;
    uint32_t u = __float_as_uint(x);
    asm("mov.b64 %0, {%1, %2};" : "=l"(d) : "r"(u), "r"(u));
    return d;
}

// ---------------- generic tiled transpose: in[R][C] -> out[C][R] ----------------
__global__ void transpose_k(const float* __restrict__ in, float* __restrict__ out,
                            int R, int C)
{
    __shared__ float t[32][33];
    int r0 = blockIdx.y * 32, c0 = blockIdx.x * 32;
#pragma unroll
    for (int i = 0; i < 32; i += 8) {
        int r = r0 + threadIdx.y + i, c = c0 + threadIdx.x;
        if (r < R && c < C) t[threadIdx.y + i][threadIdx.x] = in[(size_t)r * C + c];
    }
    __syncthreads();
#pragma unroll
    for (int i = 0; i < 32; i += 8) {
        int rr = c0 + threadIdx.y + i, cc = r0 + threadIdx.x;
        if (rr < C && cc < R) out[(size_t)rr * R + cc] = t[threadIdx.x][threadIdx.y + i];
    }
}

// ---------------- GEMM (both operands k-major), f32x2 microkernel:
//   C[n][m] = sum_k AT[k][m] * WT[k][n] + b1[n] + b2[n]
#define GBM 128
#define GBN 128
#define GBK 16

__global__ __launch_bounds__(256) void gemm_tt(
    const float* __restrict__ AT,   // [K][M]
    const float* __restrict__ WT,   // [K][N]
    const float* __restrict__ b1,
    const float* __restrict__ b2,
    float* __restrict__ C,          // [N][M]
    int M, int N, int K)
{
    __shared__ __align__(16) float As[GBK][GBM];
    __shared__ __align__(16) float Bs[GBK][GBN];
    int tid = threadIdx.x;
    int m0 = blockIdx.x * GBM, n0 = blockIdx.y * GBN;

    int lk = tid >> 5;          // loader row 0..7 (+8)
    int lq = tid & 31;          // loader float4 col
    int tm = tid & 15;          // compute: m microtile index
    int tn = tid >> 4;          // compute: n microtile index

    unsigned long long acc2[8][4];
#pragma unroll
    for (int j = 0; j < 8; j++)
#pragma unroll
        for (int i = 0; i < 4; i++) acc2[j][i] = 0ull;   // (0.f, 0.f)

    const float4 z4 = make_float4(0.f, 0.f, 0.f, 0.f);
    float4 pa[2], pb[2];
    bool nvalid = (n0 + lq * 4 + 3) < N;

#pragma unroll
    for (int i = 0; i < 2; i++) {
        int k = lk + i * 8;
        pa[i] = (k < K) ? *reinterpret_cast<const float4*>(&AT[(size_t)k * M + m0 + lq * 4]) : z4;
        pb[i] = (k < K && nvalid) ? *reinterpret_cast<const float4*>(&WT[(size_t)k * N + n0 + lq * 4]) : z4;
    }

    int nch = (K + GBK - 1) / GBK;
    for (int ch = 0; ch < nch; ch++) {
        __syncthreads();
#pragma unroll
        for (int i = 0; i < 2; i++) {
            *reinterpret_cast<float4*>(&As[lk + i * 8][lq * 4]) = pa[i];
            *reinterpret_cast<float4*>(&Bs[lk + i * 8][lq * 4]) = pb[i];
        }
        __syncthreads();
        if (ch + 1 < nch) {
            int k0 = (ch + 1) * GBK;
#pragma unroll
            for (int i = 0; i < 2; i++) {
                int k = k0 + lk + i * 8;
                pa[i] = (k < K) ? *reinterpret_cast<const float4*>(&AT[(size_t)k * M + m0 + lq * 4]) : z4;
                pb[i] = (k < K && nvalid) ? *reinterpret_cast<const float4*>(&WT[(size_t)k * N + n0 + lq * 4]) : z4;
            }
        }
#pragma unroll
        for (int kk = 0; kk < GBK; kk++) {
            ulonglong2 a01 = *reinterpret_cast<const ulonglong2*>(&As[kk][tm * 8]);
            ulonglong2 a23 = *reinterpret_cast<const ulonglong2*>(&As[kk][tm * 8 + 4]);
            float4 b0 = *reinterpret_cast<const float4*>(&Bs[kk][tn * 8]);
            float4 b1v = *reinterpret_cast<const float4*>(&Bs[kk][tn * 8 + 4]);
            float bj[8] = {b0.x, b0.y, b0.z, b0.w, b1v.x, b1v.y, b1v.z, b1v.w};
#pragma unroll
            for (int j = 0; j < 8; j++) {
                unsigned long long bb = splat2(bj[j]);
                acc2[j][0] = fma2(a01.x, bb, acc2[j][0]);
                acc2[j][1] = fma2(a01.y, bb, acc2[j][1]);
                acc2[j][2] = fma2(a23.x, bb, acc2[j][2]);
                acc2[j][3] = fma2(a23.y, bb, acc2[j][3]);
            }
        }
    }

#pragma unroll
    for (int j = 0; j < 8; j++) {
        int n = n0 + tn * 8 + j;
        if (n >= N) continue;
        float bias = (b1 ? b1[n] : 0.f) + (b2 ? b2[n] : 0.f);
        float2 p0 = unpk2(acc2[j][0]);
        float2 p1 = unpk2(acc2[j][1]);
        float2 p2 = unpk2(acc2[j][2]);
        float2 p3 = unpk2(acc2[j][3]);
        float* crow = &C[(size_t)n * M + m0 + tm * 8];
        *reinterpret_cast<float4*>(crow) =
            make_float4(p0.x + bias, p0.y + bias, p1.x + bias, p1.y + bias);
        *reinterpret_cast<float4*>(crow + 4) =
            make_float4(p2.x + bias, p2.y + bias, p3.x + bias, p3.y + bias);
    }
}

// ---------------- LSTM recurrence (cluster of 4 CTAs per batch element) ----------------
__device__ __forceinline__ float tanha(float x) {
    float y; asm("tanh.approx.f32 %0, %1;" : "=f"(y) : "f"(x)); return y;
}
__device__ __forceinline__ float sigm(float x) { return 0.5f * tanha(0.5f * x) + 0.5f; }

__device__ __forceinline__ uint32_t smem_u32(const void* p) {
    return (uint32_t)__cvta_generic_to_shared(p);
}
__device__ __forceinline__ void mbar_wait_cluster(uint32_t mbar, uint32_t parity) {
    asm volatile(
        "{\n\t.reg .pred P;\n\t"
        "WL_%=:\n\t"
        "mbarrier.try_wait.parity.acquire.cluster.shared::cta.b64 P, [%0], %1, 0x989680;\n\t"
        "@P bra.uni WD_%=;\n\t"
        "bra.uni WL_%=;\n\t"
        "WD_%=:\n\t}"
        :: "r"(mbar), "r"(parity) : "memory");
}

__global__ __launch_bounds__(192, 1) __cluster_dims__(4, 1, 1)
void lstm_recur(const float* __restrict__ Whh_l,   // [720][180] this layer (row-major)
                const float* __restrict__ G,       // [720][M] preact incl. biases
                float* __restrict__ HT)            // [180][M] out (transposed)
{
    __shared__ __align__(16) float h_sh[2][184];   // double-buffered hidden state
    __shared__ __align__(16) float pre_sh[184];
    __shared__ __align__(8) unsigned long long mbar[2];

    int t = threadIdx.x;
    int batch = blockIdx.x >> 2;
    int rank  = blockIdx.x & 3;
    int u0 = rank * 45;              // this CTA owns hidden units [u0, u0+45)
    bool act = (t < 180);
    int gate = t / 45;
    int uu = t - gate * 45;
    int row_global = gate * 180 + u0 + uu;   // (i,f,g,o) blocks of 180

    // entire Whh row in registers as 90 packed f32x2
    unsigned long long w2[90];
    if (act) {
        const ulonglong2* wr =
            reinterpret_cast<const ulonglong2*>(Whh_l + (size_t)row_global * Hsz);
#pragma unroll
        for (int k = 0; k < 45; k++) { ulonglong2 v = wr[k]; w2[2 * k] = v.x; w2[2 * k + 1] = v.y; }
    }
    if (t < 184) { h_sh[0][t] = 0.f; h_sh[1][t] = 0.f; }
    uint32_t mb0 = smem_u32(&mbar[0]);
    uint32_t mb1 = smem_u32(&mbar[1]);
    if (t == 0) {
        asm volatile("mbarrier.init.shared.b64 [%0], 1;" :: "r"(mb0) : "memory");
        asm volatile("mbarrier.init.shared.b64 [%0], 1;" :: "r"(mb1) : "memory");
    }
    float c = 0.f;

    const float* Grow = G + (act ? ((size_t)row_global * Msz + batch * Ssz) : 0);
    float gnext = act ? Grow[0] : 0.f;
    float* Hrow = HT + (size_t)(u0 + (t < 45 ? t : 0)) * Msz + batch * Ssz;

    // one-time cluster barrier: buffers zeroed + mbars initialized everywhere
    asm volatile("barrier.cluster.arrive.aligned;" ::: "memory");
    asm volatile("barrier.cluster.wait.aligned;" ::: "memory");

    uint32_t ph0 = 0, ph1 = 0;
    for (int s = 0; s < Ssz; s++) {
        int cur = s & 1;
        if (s > 0) {          // h(s) delivery: 720 B of tx into buf[cur]'s mbar
            if (cur) { mbar_wait_cluster(mb1, ph1); ph1 ^= 1; }
            else     { mbar_wait_cluster(mb0, ph0); ph0 ^= 1; }
        }
        float gv = gnext;
        if (act && s + 1 < Ssz) gnext = Grow[s + 1];   // prefetch across step

        if (act) {
            const ulonglong2* hb = reinterpret_cast<const ulonglong2*>(h_sh[cur]);
            unsigned long long A0 = 0ull, A1 = 0ull;
#pragma unroll
            for (int k = 0; k < 45; k++) {
                ulonglong2 h2 = hb[k];
                A0 = fma2(w2[2 * k],     h2.x, A0);
                A1 = fma2(w2[2 * k + 1], h2.y, A1);
            }
            float2 r0 = unpk2(A0), r1 = unpk2(A1);
            pre_sh[t] = ((r0.x + r0.y) + (r1.x + r1.y)) + gv;
        }
        __syncthreads();   // pre_sh complete for this step

        int nxt = cur ^ 1;
        uint32_t mbl = nxt ? mb1 : mb0;
        if ((s + 1 < Ssz) && t == 0) {
            // arm delivery of h(s+1): 180 floats = 720 bytes of tx
            asm volatile("mbarrier.arrive.expect_tx.shared.b64 _, [%0], %1;"
                         :: "r"(mbl), "r"(720u) : "memory");
        }
        if (t < 45) {
            float gi = pre_sh[t];
            float gf = pre_sh[45 + t];
            float gg = pre_sh[90 + t];
            float go = pre_sh[135 + t];
            c = sigm(gf) * c + sigm(gi) * tanha(gg);
            float hn = sigm(go) * tanha(c);
            Hrow[s] = hn;
            if (s + 1 < Ssz) {
                uint32_t la = smem_u32(&h_sh[nxt][u0 + t]);
                uint32_t hv = __float_as_uint(hn);
#pragma unroll
                for (uint32_t p = 0; p < 4; p++) {
                    uint32_t ra, rm;
                    asm volatile("mapa.shared::cluster.u32 %0, %1, %2;" : "=r"(ra) : "r"(la), "r"(p));
                    asm volatile("mapa.shared::cluster.u32 %0, %1, %2;" : "=r"(rm) : "r"(mbl), "r"(p));
                    asm volatile("st.async.shared::cluster.mbarrier::complete_tx::bytes.b32 [%0], %1, [%2];"
                                 :: "r"(ra), "r"(hv), "r"(rm) : "memory");
                }
            }
        }
        // no trailing barrier: next step's mbar wait includes our own CTA's
        // writers' tx (issued after their pre_sh reads), so both the h-buffer
        // publish AND the pre_sh WAR hazard are ordered by the mbar.
    }
}

// ---------------- mel smoothing block on [60][M] layout ----------------
__global__ void mel_T(const float* __restrict__ X, const float* __restrict__ w,
                      const float* __restrict__ bias, float* __restrict__ Y, int l)
{
    int m = blockIdx.x * 256 + threadIdx.x;   // 0..M-1
    int cch = blockIdx.y;                     // 0..59
    int s = m & (Ssz - 1);
    int j = cch % 3, i = cch / 3;
    const float* wp = w + ((size_t)(l * 3 + j) * 20 + i) * 15;
    float acc = X[(size_t)cch * Msz + m] + bias[(l * 3 + j) * 20 + i];
#pragma unroll
    for (int d = 0; d < 3; d++) {
        int cc = cch + d - 1;
        if (cc < 0 || cc >= OUTsz) continue;
        const float* row = X + (size_t)cc * Msz + m;
#pragma unroll
        for (int k = 0; k < 5; k++) {
            int ss = s + k - 2;
            if (ss < 0 || ss >= Ssz) continue;
            acc += row[k - 2] * wp[d * 5 + k];
        }
    }
    Y[(size_t)cch * Msz + m] = acc;
}

// ---------------- residual conv on [60][M]; writes m-major output ----------------
__global__ void res_T(const float* __restrict__ Lm, const float* __restrict__ Sm,
                      const float* __restrict__ resW, const float* __restrict__ resb,
                      float* __restrict__ Y)
{
    int m = blockIdx.x * 256 + threadIdx.x;
    int cch = blockIdx.y;
    int s = m & (Ssz - 1);
    const float* Lr = Lm + (size_t)cch * Msz + m;
    const float* Sr = Sm + (size_t)cch * Msz + m;
    float acc = resb[cch];
#pragma unroll
    for (int k = 0; k < 5; k++) {
        int ss = s + k - 2;
        if (ss < 0 || ss >= Ssz) continue;
        acc += Lr[k - 2] * resW[cch * 10 + k];
        acc += Sr[k - 2] * resW[cch * 10 + 5 + k];
    }
    Y[(size_t)m * OUTsz + cch] = acc;   // [B,S,60]
}

// ---------------- launcher ----------------
extern "C" void kernel_launch(void* const* d_in, const int* in_sizes, int n_in,
                              void* d_out, int out_size)
{
    const float* x        = (const float*)d_in[0];
    const float* Wih0     = (const float*)d_in[1];
    const float* Wih_rest = (const float*)d_in[2];
    const float* Whh      = (const float*)d_in[3];
    const float* bih      = (const float*)d_in[4];
    const float* bhh      = (const float*)d_in[5];
    const float* linW     = (const float*)d_in[6];
    const float* linb     = (const float*)d_in[7];
    const float* mel_w    = (const float*)d_in[8];
    const float* mel_b    = (const float*)d_in[9];
    const float* resW     = (const float*)d_in[10];
    const float* resb     = (const float*)d_in[11];
    float* out = (float*)d_out;

    float *pXT, *pWT, *pG, *pHT, *pLin, *pA, *pB;
    cudaGetSymbolAddress((void**)&pXT,  g_xT);
    cudaGetSymbolAddress((void**)&pWT,  g_WT);
    cudaGetSymbolAddress((void**)&pG,   g_G);
    cudaGetSymbolAddress((void**)&pHT,  g_HT);
    cudaGetSymbolAddress((void**)&pLin, g_linT);
    cudaGetSymbolAddress((void**)&pA,   g_mA);
    cudaGetSymbolAddress((void**)&pB,   g_mB);

    dim3 tb(32, 8);
    auto tgrid = [](int R, int C) { return dim3((C + 31) / 32, (R + 31) / 32); };

    // x^T : [M,300] -> [300,M]
    transpose_k<<<tgrid(Msz, INsz), tb>>>(x, pXT, Msz, INsz);

    dim3 gblk(256);
    dim3 gg(Msz / GBM, (GHsz + GBN - 1) / GBN);   // 128 x 6

    // layer 0
    transpose_k<<<tgrid(GHsz, INsz), tb>>>(Wih0, pWT, GHsz, INsz);
    gemm_tt<<<gg, gblk>>>(pXT, pWT, bih, bhh, pG, Msz, GHsz, INsz);
    lstm_recur<<<128, 192>>>(Whh, pG, pHT);

    // layers 1..3
    for (int l = 1; l < 4; l++) {
        transpose_k<<<tgrid(GHsz, Hsz), tb>>>(Wih_rest + (size_t)(l - 1) * GHsz * Hsz,
                                              pWT, GHsz, Hsz);
        gemm_tt<<<gg, gblk>>>(pHT, pWT, bih + l * GHsz, bhh + l * GHsz,
                              pG, Msz, GHsz, Hsz);
        lstm_recur<<<128, 192>>>(Whh + (size_t)l * GHsz * Hsz, pG, pHT);
    }

    // linear to 60 channels, output [60][M]
    transpose_k<<<tgrid(OUTsz, Hsz), tb>>>(linW, pWT, OUTsz, Hsz);
    dim3 gl(Msz / GBM, 1);
    gemm_tt<<<gl, gblk>>>(pHT, pWT, linb, nullptr, pLin, Msz, OUTsz, Hsz);

    // mel smoothing blocks + residual conv
    dim3 cgrid(Msz / 256, OUTsz);
    mel_T<<<cgrid, 256>>>(pLin, mel_w, mel_b, pA, 0);
    mel_T<<<cgrid, 256>>>(pA,   mel_w, mel_b, pB, 1);
    mel_T<<<cgrid, 256>>>(pB,   mel_w, mel_b, pA, 2);
    res_T<<<cgrid, 256>>>(pLin, pA, resW, resb, out);
}